// round 10
// baseline (speedup 1.0000x reference)
#include <cuda_runtime.h>
#include <math.h>
#include <float.h>
#include <stdint.h>

#define BB      64
#define TT      100
#define NQ      (BB * TT)          // 6400 queries
#define NN      20000
#define NCH     16
#define CH_PTS  1250               // real points per chunk
#define CH_PAD  1280               // padded points per chunk
#define CH_PAIR 640                // pairs per chunk
#define WARPS   4
#define WPAIR   (CH_PAIR / WARPS)  // 160 pairs per warp
#define SEGPAIR 16                 // pairs per segment (32 points)
#define NSEG    (WPAIR / SEGPAIR)  // 10 segments per warp
#define SEGPTS  (SEGPAIR * 2)      // 32 points
#define NTILE   (NQ / 128)         // 50 query tiles
#define THREADS 128

// Scratch (no device allocation allowed)
__device__ float g_pmin[NTILE * NCH * 128];   // [tile][ch][slot] - coalesced
__device__ int   g_ps0 [NTILE * NCH * 128];   // padded start of winning 32-pt segment
__device__ float g_tile[NTILE];
__device__ int   g_tcnt[NTILE];               // per-tile arrival counters (reset in-kernel)
__device__ int   g_fcnt = 0;                  // final counter (reset in-kernel)

// ---- packed f32x2 helpers -------------------------------------------------
__device__ __forceinline__ uint64_t ffma2(uint64_t a, uint64_t b, uint64_t c) {
    uint64_t d;
    asm("fma.rn.f32x2 %0, %1, %2, %3;" : "=l"(d) : "l"(a), "l"(b), "l"(c));
    return d;
}
__device__ __forceinline__ uint64_t pack2(float v) {
    uint64_t r;
    asm("mov.b64 %0, {%1, %1};" : "=l"(r) : "f"(v));
    return r;
}
__device__ __forceinline__ void unpack2(float& lo, float& hi, uint64_t v) {
    asm("mov.b64 {%0, %1}, %2;" : "=f"(lo), "=f"(hi) : "l"(v));
}
__device__ __forceinline__ void lds_v2b64(uint64_t& a, uint64_t& b, uint32_t addr) {
    asm volatile("ld.shared.v2.b64 {%0, %1}, [%2];" : "=l"(a), "=l"(b) : "r"(addr));
}
__device__ __forceinline__ uint32_t smem_u32(const void* p) {
    uint32_t a;
    asm("{ .reg .u64 t; cvta.to.shared.u64 t, %1; cvt.u32.u64 %0, t; }"
        : "=r"(a) : "l"(p));
    return a;
}

// Query transform: local waypoint -> NEGATED global point. Must be the exact
// same fmaf chain everywhere (bitwise-identical for equality recovery).
__device__ __forceinline__ void query_transform(
    const float* __restrict__ poses, const float* __restrict__ wpts, int qid,
    float& nwx, float& nwy, float& nwz)
{
    const float* P = poses + (qid / TT) * 16;
    const float* w = wpts + qid * 3;
    const float wx = w[0], wy = w[1], wz = w[2];
    nwx = -fmaf(P[0], wx, fmaf(P[1], wy, fmaf(P[2],  wz, P[3])));
    nwy = -fmaf(P[4], wx, fmaf(P[5], wy, fmaf(P[6],  wz, P[7])));
    nwz = -fmaf(P[8], wx, fmaf(P[9], wy, fmaf(P[10], wz, P[11])));
}

// ---------------------------------------------------------------------------
// Fused kernel: CTA = (chunk, tile), 4 warps, 8 CTAs/SM -> 800 CTAs resident
// in ONE wave. Mainloop: pair-interleaved SMEM tile, FFMA2 scan, 4 slots/lane,
// segment-granular (32-pt) argmin. The 16th CTA to finish a tile (atomic
// counter) runs that tile's epilogue overlapped with other tiles' mainloops;
// the 50th tile-epilogue computes the final scalar. Fixed-order sums ->
// bitwise-deterministic output; counters self-reset for graph replay.
// ---------------------------------------------------------------------------
__global__ void __launch_bounds__(THREADS, 8) fused_kernel(
    const float* __restrict__ poses,     // [B,4,4]
    const float* __restrict__ wpts,      // [B,T,3]
    const float* __restrict__ boundary,  // [4,N]
    const float* __restrict__ nrms,      // [3,N]
    float* __restrict__ out)
{
    __shared__ float s_pts[CH_PAD * 4];     // 20 KB, pair-interleaved
    __shared__ float s_qx[128], s_qy[128], s_qz[128];
    __shared__ float red_q[WARPS][128];
    __shared__ int   red_s[WARPS][128];
    __shared__ int   s_last;

    const int ch   = blockIdx.x;
    const int tile = blockIdx.y;
    const int tid  = threadIdx.x;
    const int warp = tid >> 5;
    const int lane = tid & 31;

    // ---- build chunk tile + query transforms in SMEM ----
    const int gbase = ch * CH_PTS;
    #pragma unroll
    for (int i = tid; i < CH_PAD; i += THREADS) {
        float x = 0.0f, y = 0.0f, z = 0.0f, c = 1e30f;   // pad never wins
        if (i < CH_PTS) {
            x = boundary[0 * NN + gbase + i];
            y = boundary[1 * NN + gbase + i];
            z = boundary[2 * NN + gbase + i];
            c = 0.5f * fmaf(x, x, fmaf(y, y, z * z));
        }
        const int m = i >> 1, h = i & 1;
        s_pts[m * 8 + 0 + h] = x;
        s_pts[m * 8 + 2 + h] = y;
        s_pts[m * 8 + 4 + h] = z;
        s_pts[m * 8 + 6 + h] = c;
    }
    {
        float nwx, nwy, nwz;
        query_transform(poses, wpts, tile * 128 + tid, nwx, nwy, nwz);
        s_qx[tid] = nwx; s_qy[tid] = nwy; s_qz[tid] = nwz;
    }
    __syncthreads();

    // ---- mainloop: 160 pairs per warp, 4 query slots per lane ----
    uint64_t nwx2[4], nwy2[4], nwz2[4];
    #pragma unroll
    for (int j = 0; j < 4; ++j) {
        const int sl = lane + 32 * j;
        nwx2[j] = pack2(s_qx[sl]);
        nwy2[j] = pack2(s_qy[sl]);
        nwz2[j] = pack2(s_qz[sl]);
    }

    float best[4];
    int   sid[4];
    #pragma unroll
    for (int j = 0; j < 4; ++j) { best[j] = FLT_MAX; sid[j] = 0; }

    const uint32_t wbase = smem_u32(s_pts) + (uint32_t)(warp * WPAIR) * 32u;

    #pragma unroll
    for (int s = 0; s < NSEG; ++s) {
        const uint32_t segb = wbase + (uint32_t)(s * SEGPAIR) * 32u;
        float svlo[4], svhi[4];
        #pragma unroll
        for (int j = 0; j < 4; ++j) { svlo[j] = FLT_MAX; svhi[j] = FLT_MAX; }

        #pragma unroll 4
        for (int pp = 0; pp < SEGPAIR; ++pp) {
            uint64_t xx, yy, zz, cc;
            lds_v2b64(xx, yy, segb + pp * 32u);        // broadcast
            lds_v2b64(zz, cc, segb + pp * 32u + 16u);
            #pragma unroll
            for (int j = 0; j < 4; ++j) {
                uint64_t q = ffma2(nwx2[j], xx,
                             ffma2(nwy2[j], yy,
                             ffma2(nwz2[j], zz, cc)));
                float qlo, qhi;
                unpack2(qlo, qhi, q);                   // free register alias
                svlo[j] = fminf(svlo[j], qlo);
                svhi[j] = fminf(svhi[j], qhi);
            }
        }
        #pragma unroll
        for (int j = 0; j < 4; ++j) {
            float m = fminf(svlo[j], svhi[j]);
            sid[j]  = (m < best[j]) ? s : sid[j];       // strict < -> first seg
            best[j] = fminf(best[j], m);
        }
    }

    #pragma unroll
    for (int j = 0; j < 4; ++j) {
        red_q[warp][lane + 32 * j] = best[j];
        red_s[warp][lane + 32 * j] = ch * CH_PAD + (warp * WPAIR + sid[j] * SEGPAIR) * 2;
    }
    __syncthreads();

    // cross-warp reduce (slot = tid); strict < keeps lowest warp = lowest n
    {
        float bq = red_q[0][tid];
        int   bs = red_s[0][tid];
        #pragma unroll
        for (int w = 1; w < WARPS; ++w) {
            float q = red_q[w][tid];
            int   s = red_s[w][tid];
            if (q < bq) { bq = q; bs = s; }
        }
        g_pmin[(tile * NCH + ch) * 128 + tid] = bq;     // coalesced
        g_ps0 [(tile * NCH + ch) * 128 + tid] = bs;
    }
    __threadfence();
    if (tid == 0) {
        const int old = atomicAdd(&g_tcnt[tile], 1);
        s_last = (old == NCH - 1) ? 1 : 0;
        if (s_last) g_tcnt[tile] = 0;                   // replay-safe reset
    }
    __syncthreads();
    if (!s_last) return;

    // ---- tile epilogue (runs on the 16th CTA, overlapped chip-wide) ----
    // Thread t owns query qid = tile*128 + t.
    float val;
    {
        const int qid = tile * 128 + tid;
        const float nwx = s_qx[tid], nwy = s_qy[tid], nwz = s_qz[tid];

        float vmin = FLT_MAX;
        int   s0   = 0x7FFFFFFF;
        #pragma unroll
        for (int c = 0; c < NCH; ++c) {                 // ascending ch: strict <
            float q = g_pmin[(tile * NCH + c) * 128 + tid];  // coalesced
            int   s = g_ps0 [(tile * NCH + c) * 128 + tid];
            if (q < vmin) { vmin = q; s0 = s; }
        }

        // rescan the winning 32-pt segment; identical fmaf chain -> exact
        const int wch  = s0 / CH_PAD;
        const int offb = s0 - wch * CH_PAD;
        int nbest = 0x7FFFFFFF;
        #pragma unroll 8
        for (int k = 0; k < SEGPTS; ++k) {
            const int o = offb + k;
            if (o < CH_PTS) {
                const int n = wch * CH_PTS + o;
                float x = boundary[0 * NN + n];
                float y = boundary[1 * NN + n];
                float z = boundary[2 * NN + n];
                float c = 0.5f * fmaf(x, x, fmaf(y, y, z * z));
                float q = fmaf(nwx, x, fmaf(nwy, y, fmaf(nwz, z, c)));
                if (q == vmin && n < nbest) nbest = n;  // first match = lowest n
            }
        }
        const int n = nbest;
        const float cpx = boundary[0 * NN + n];
        const float cpy = boundary[1 * NN + n];
        const float cpz = boundary[2 * NN + n];
        const float nx  = nrms[0 * NN + n];
        const float ny  = nrms[1 * NN + n];
        const float nz  = nrms[2 * NN + n];
        // global-frame dot: (wg - cp) . n_g  (rigid transform cancels)
        const float d = (-nwx - cpx) * nx + (-nwy - cpy) * ny + (-nwz - cpz) * nz;
        val = (d > 0.0f) ? (d + 1.0f) : expf(0.5f * d); // ExpRelu a=1, b=0.5
        (void)qid;
    }

    // CTA sum of 128 query values (fixed tree order -> deterministic)
    __shared__ float acc[128];
    acc[tid] = val;
    __syncthreads();
    #pragma unroll
    for (int o = 64; o > 0; o >>= 1) {
        if (tid < o) acc[tid] += acc[tid + o];
        __syncthreads();
    }
    if (tid == 0) {
        g_tile[tile] = acc[0];
        __threadfence();
        const int old = atomicAdd(&g_fcnt, 1);
        if (old == NTILE - 1) {
            // final: fixed ascending order -> deterministic
            float s = 0.0f;
            #pragma unroll 10
            for (int k = 0; k < NTILE; ++k) s += g_tile[k];
            out[0] = s * (1.0f / (float)NQ);
            g_fcnt = 0;                                 // replay-safe reset
        }
    }
}

// ---------------------------------------------------------------------------
extern "C" void kernel_launch(void* const* d_in, const int* in_sizes, int n_in,
                              void* d_out, int out_size)
{
    const float* poses    = (const float*)d_in[0];  // [64,4,4]
    const float* wpts     = (const float*)d_in[1];  // [64,100,3]
    const float* boundary = (const float*)d_in[2];  // [4,20000]
    const float* nrms     = (const float*)d_in[3];  // [3,20000]
    float* out = (float*)d_out;

    dim3 grid(NCH, NTILE);
    fused_kernel<<<grid, THREADS>>>(poses, wpts, boundary, nrms, out);
}

// round 11
// speedup vs baseline: 1.5544x; 1.5544x over previous
#include <cuda_runtime.h>
#include <math.h>
#include <float.h>
#include <stdint.h>

#define BB      64
#define TT      100
#define NQ      (BB * TT)          // 6400 queries (flat)
#define NN      20000
#define NCH     16
#define CH_PTS  1250               // real points per chunk
#define CH_PAD  1280               // padded points per chunk
#define CH_PAIR 640                // pairs per chunk
#define WARPS   8
#define WPAIR   (CH_PAIR / WARPS)  // 80 pairs per warp
#define SEGPAIR 16                 // pairs per segment
#define NSEG    (WPAIR / SEGPAIR)  // 5 segments per warp
#define SEGPTS  (SEGPAIR * 2)      // 32 points per segment
#define NTILE   (NQ / 128)         // 50 query tiles
#define THREADS 256
#define NRED    (NQ / 8)           // 800 reduce CTAs

// Scratch (no device allocation allowed)
__device__ float g_pmin[NQ * NCH];
__device__ int   g_ps0 [NQ * NCH];   // padded-index start of winning 32-pt segment
__device__ float g_part[NRED];
__device__ int   g_cnt = 0;          // threadfence-reduction counter (self-reset)

// ---- packed f32x2 helpers -------------------------------------------------
__device__ __forceinline__ uint64_t ffma2(uint64_t a, uint64_t b, uint64_t c) {
    uint64_t d;
    asm("fma.rn.f32x2 %0, %1, %2, %3;" : "=l"(d) : "l"(a), "l"(b), "l"(c));
    return d;
}
__device__ __forceinline__ uint64_t pack2(float v) {
    uint64_t r;
    asm("mov.b64 %0, {%1, %1};" : "=l"(r) : "f"(v));
    return r;
}
__device__ __forceinline__ void unpack2(float& lo, float& hi, uint64_t v) {
    asm("mov.b64 {%0, %1}, %2;" : "=f"(lo), "=f"(hi) : "l"(v));
}
__device__ __forceinline__ void lds_v2b64(uint64_t& a, uint64_t& b, uint32_t addr) {
    asm volatile("ld.shared.v2.b64 {%0, %1}, [%2];" : "=l"(a), "=l"(b) : "r"(addr));
}
__device__ __forceinline__ uint32_t smem_u32(const void* p) {
    uint32_t a;
    asm("{ .reg .u64 t; cvta.to.shared.u64 t, %1; cvt.u32.u64 %0, t; }"
        : "=r"(a) : "l"(p));
    return a;
}

// Query transform: local waypoint -> NEGATED global point. Must be the exact
// same fmaf chain in both kernels (bitwise-identical for equality recovery).
__device__ __forceinline__ void query_transform(
    const float* __restrict__ poses, const float* __restrict__ wpts, int qid,
    float& nwx, float& nwy, float& nwz)
{
    const float* P = poses + (qid / TT) * 16;
    const float* w = wpts + qid * 3;
    const float wx = w[0], wy = w[1], wz = w[2];
    nwx = -fmaf(P[0], wx, fmaf(P[1], wy, fmaf(P[2],  wz, P[3])));
    nwy = -fmaf(P[4], wx, fmaf(P[5], wy, fmaf(P[6],  wz, P[7])));
    nwz = -fmaf(P[8], wx, fmaf(P[9], wy, fmaf(P[10], wz, P[11])));
}

// ---------------------------------------------------------------------------
// NN kernel: CTA = (chunk, query-tile). Builds the chunk tile (x,y,z,0.5|p|^2,
// pair-interleaved) and 128 query transforms in SMEM; each warp scans its 80
// pairs (5 segments of 16) for 128 query slots (4/lane, zero padding) with
// FFMA2 + two scalar FMNMX chains per slot. Segment-granular argmin: only
// (min value, 32-pt segment start) survives. Cross-warp SMEM reduce -> one
// partial per (query, chunk).
// ---------------------------------------------------------------------------
__global__ void __launch_bounds__(THREADS, 4) nn_kernel(
    const float* __restrict__ poses,     // [B,4,4]
    const float* __restrict__ wpts,      // [B,T,3]
    const float* __restrict__ boundary)  // [4,N]
{
    __shared__ float s_pts[CH_PAD * 4];     // 20 KB, pair-interleaved
    __shared__ float s_qx[128], s_qy[128], s_qz[128];
    __shared__ float red_q[WARPS][128];     // 4 KB
    __shared__ int   red_s[WARPS][128];     // 4 KB

    const int ch   = blockIdx.x;
    const int tile = blockIdx.y;
    const int tid  = threadIdx.x;

    // Build chunk tile (identical math to reduce's recompute)
    const int gbase = ch * CH_PTS;
    for (int i = tid; i < CH_PAD; i += THREADS) {
        float x = 0.0f, y = 0.0f, z = 0.0f, c = 1e30f;   // pad never wins
        if (i < CH_PTS) {
            x = boundary[0 * NN + gbase + i];
            y = boundary[1 * NN + gbase + i];
            z = boundary[2 * NN + gbase + i];
            c = 0.5f * fmaf(x, x, fmaf(y, y, z * z));
        }
        const int m = i >> 1, h = i & 1;
        s_pts[m * 8 + 0 + h] = x;
        s_pts[m * 8 + 2 + h] = y;
        s_pts[m * 8 + 4 + h] = z;
        s_pts[m * 8 + 6 + h] = c;
    }
    if (tid < 128) {
        float nwx, nwy, nwz;
        query_transform(poses, wpts, tile * 128 + tid, nwx, nwy, nwz);
        s_qx[tid] = nwx; s_qy[tid] = nwy; s_qz[tid] = nwz;
    }
    __syncthreads();

    const int warp = tid >> 5;
    const int lane = tid & 31;

    uint64_t nwx2[4], nwy2[4], nwz2[4];
    #pragma unroll
    for (int j = 0; j < 4; ++j) {
        const int sl = lane + 32 * j;
        nwx2[j] = pack2(s_qx[sl]);
        nwy2[j] = pack2(s_qy[sl]);
        nwz2[j] = pack2(s_qz[sl]);
    }

    float best[4];
    int   sid[4];
    #pragma unroll
    for (int j = 0; j < 4; ++j) { best[j] = FLT_MAX; sid[j] = 0; }

    const uint32_t wbase = smem_u32(s_pts) + (uint32_t)(warp * WPAIR) * 32u;

    #pragma unroll
    for (int s = 0; s < NSEG; ++s) {
        const uint32_t segb = wbase + (uint32_t)(s * SEGPAIR) * 32u;
        float svlo[4], svhi[4];
        #pragma unroll
        for (int j = 0; j < 4; ++j) { svlo[j] = FLT_MAX; svhi[j] = FLT_MAX; }

        #pragma unroll 4
        for (int pp = 0; pp < SEGPAIR; ++pp) {
            uint64_t xx, yy, zz, cc;
            lds_v2b64(xx, yy, segb + pp * 32u);        // broadcast, conflict-free
            lds_v2b64(zz, cc, segb + pp * 32u + 16u);
            #pragma unroll
            for (int j = 0; j < 4; ++j) {
                uint64_t q = ffma2(nwx2[j], xx,
                             ffma2(nwy2[j], yy,
                             ffma2(nwz2[j], zz, cc)));
                float qlo, qhi;
                unpack2(qlo, qhi, q);                   // register alias, free
                svlo[j] = fminf(svlo[j], qlo);
                svhi[j] = fminf(svhi[j], qhi);
            }
        }
        #pragma unroll
        for (int j = 0; j < 4; ++j) {
            float m = fminf(svlo[j], svhi[j]);
            sid[j]  = (m < best[j]) ? s : sid[j];       // strict < -> first seg
            best[j] = fminf(best[j], m);
        }
    }

    #pragma unroll
    for (int j = 0; j < 4; ++j) {
        red_q[warp][lane + 32 * j] = best[j];
        red_s[warp][lane + 32 * j] =
            ch * CH_PAD + (warp * WPAIR + sid[j] * SEGPAIR) * 2;
    }
    __syncthreads();

    // Cross-warp reduce; strict < keeps lowest warp = lowest point index.
    if (tid < 128) {
        float bq = red_q[0][tid];
        int   bs = red_s[0][tid];
        #pragma unroll
        for (int w = 1; w < WARPS; ++w) {
            float q = red_q[w][tid];
            int   s = red_s[w][tid];
            if (q < bq) { bq = q; bs = s; }
        }
        const int qid = tile * 128 + tid;
        g_pmin[qid * NCH + ch] = bq;
        g_ps0 [qid * NCH + ch] = bs;
    }
}

// ---------------------------------------------------------------------------
// Reduce + final: warp per query. 16-partial shuffle argmin (tie -> lowest
// segment start = lowest n), single coalesced 32-pt rescan recomputing the
// bitwise-identical fma chain, dot with global normal (rotation cancels),
// ExpRelu, CTA sum. Last CTA sums the 800 partials in fixed order.
// ---------------------------------------------------------------------------
__global__ void __launch_bounds__(THREADS) reduce_kernel(
    const float* __restrict__ poses,
    const float* __restrict__ wpts,
    const float* __restrict__ boundary,
    const float* __restrict__ nrms,      // [3,N] global normals
    float* __restrict__ out)
{
    const int warp = threadIdx.x >> 5;
    const int lane = threadIdx.x & 31;
    const int qid  = blockIdx.x * 8 + warp;

    float nwx, nwy, nwz;
    query_transform(poses, wpts, qid, nwx, nwy, nwz);

    float vmin = FLT_MAX;
    int   s0   = 0x7FFFFFFF;
    if (lane < NCH) {
        vmin = g_pmin[qid * NCH + lane];
        s0   = g_ps0 [qid * NCH + lane];
    }
    #pragma unroll
    for (int off = 16; off > 0; off >>= 1) {
        float v2 = __shfl_xor_sync(0xFFFFFFFFu, vmin, off);
        int   s2 = __shfl_xor_sync(0xFFFFFFFFu, s0,   off);
        if (v2 < vmin || (v2 == vmin && s2 < s0)) { vmin = v2; s0 = s2; }
    }

    // Single 32-pt rescan (one point per lane); exact-equality recovery.
    const int ch   = s0 / CH_PAD;
    const int offb = s0 - ch * CH_PAD;
    int nbest = 0x7FFFFFFF;
    {
        const int o = offb + lane;
        if (o < CH_PTS) {
            const int n = ch * CH_PTS + o;
            float x = boundary[0 * NN + n];
            float y = boundary[1 * NN + n];
            float z = boundary[2 * NN + n];
            float c = 0.5f * fmaf(x, x, fmaf(y, y, z * z));
            float q = fmaf(nwx, x, fmaf(nwy, y, fmaf(nwz, z, c)));
            if (q == vmin) nbest = n;
        }
    }
    #pragma unroll
    for (int off = 16; off > 0; off >>= 1)
        nbest = min(nbest, __shfl_xor_sync(0xFFFFFFFFu, nbest, off));

    __shared__ float sh[8];
    if (lane == 0) {
        const int n = nbest;
        const float cpx = boundary[0 * NN + n];
        const float cpy = boundary[1 * NN + n];
        const float cpz = boundary[2 * NN + n];
        const float nx  = nrms[0 * NN + n];
        const float ny  = nrms[1 * NN + n];
        const float nz  = nrms[2 * NN + n];
        // global-frame dot: (wg - cp) . n_g  (rigid transform cancels)
        const float d = (-nwx - cpx) * nx + (-nwy - cpy) * ny + (-nwz - cpz) * nz;
        sh[warp] = (d > 0.0f) ? (d + 1.0f) : expf(0.5f * d);  // ExpRelu a=1,b=.5
    }
    __syncthreads();

    __shared__ int s_last;
    if (threadIdx.x == 0) {
        float s = 0.0f;
        #pragma unroll
        for (int w = 0; w < 8; ++w) s += sh[w];
        g_part[blockIdx.x] = s;
        __threadfence();
        const int old = atomicAdd(&g_cnt, 1);
        s_last = (old == NRED - 1) ? 1 : 0;
    }
    __syncthreads();

    if (s_last) {
        __shared__ float acc[THREADS];
        const int tid = threadIdx.x;
        float s = 0.0f;
        for (int k = tid; k < NRED; k += THREADS) s += g_part[k];
        acc[tid] = s;
        __syncthreads();
        #pragma unroll
        for (int o = THREADS / 2; o > 0; o >>= 1) {
            if (tid < o) acc[tid] += acc[tid + o];
            __syncthreads();
        }
        if (tid == 0) {
            out[0] = acc[0] * (1.0f / (float)NQ);
            g_cnt = 0;   // replay-safe reset
        }
    }
}

// ---------------------------------------------------------------------------
extern "C" void kernel_launch(void* const* d_in, const int* in_sizes, int n_in,
                              void* d_out, int out_size)
{
    const float* poses    = (const float*)d_in[0];  // [64,4,4]
    const float* wpts     = (const float*)d_in[1];  // [64,100,3]
    const float* boundary = (const float*)d_in[2];  // [4,20000]
    const float* nrms     = (const float*)d_in[3];  // [3,20000]
    float* out = (float*)d_out;

    dim3 gridn(NCH, NTILE);
    nn_kernel<<<gridn, THREADS>>>(poses, wpts, boundary);
    reduce_kernel<<<NRED, THREADS>>>(poses, wpts, boundary, nrms, out);
}